// round 13
// baseline (speedup 1.0000x reference)
#include <cuda_runtime.h>
#include <cuda_fp16.h>
#include <cstdint>
#include <math.h>

// ---------------- problem constants ----------------
#define B_SZ     256
#define N_TOK    197
#define D_L      512
#define D_G      768
#define M_FINE   (B_SZ * N_TOK)          // 50432
#define TOPK     5

#define OFF_G    0
#define OFF_LS   (B_SZ * D_G)                         // 196608
#define OFF_FINE (OFF_LS + 1)                         // 196609
#define OFF_TOP  (OFF_FINE + (size_t)M_FINE * D_L)

#define LO_SCALE     2048.0f
#define INV_LO_SCALE (1.0f / 2048.0f)

// ---------------- device scratch (weights pre-split fp16 hi / lo*2048) ----------------
__device__ __align__(16) __half g_W1h[D_L * D_L], g_W1l[D_L * D_L];
__device__ __align__(16) __half g_W2h[D_L * D_L], g_W2l[D_L * D_L];
__device__ __align__(16) __half g_V1h[D_G * D_L], g_V1l[D_G * D_L];
__device__ __align__(16) __half g_V2h[D_G * D_G], g_V2l[D_G * D_G];
__device__ __align__(16) float g_Hf[(size_t)M_FINE * D_L];
__device__ __align__(16) float g_Hg[B_SZ * D_G];
__device__ __align__(16) float g_G [B_SZ * D_G];
__device__ __align__(16) float g_sums_f[2 * D_L];
__device__ __align__(16) float g_sums_g[2 * D_G];
__device__ __align__(16) float g_scale_f[D_L], g_shift_f[D_L];
__device__ __align__(16) float g_scale_g[D_G], g_shift_g[D_G];

// ---------------- helpers ----------------
__device__ __forceinline__ uint32_t s2u(const void* p) {
    uint32_t a;
    asm("{ .reg .u64 t; cvta.to.shared.u64 t, %1; cvt.u32.u64 %0, t; }" : "=r"(a) : "l"(p));
    return a;
}
__device__ __forceinline__ void ldsm_x4(uint32_t* r, uint32_t addr) {
    asm volatile("ldmatrix.sync.aligned.m8n8.x4.shared.b16 {%0,%1,%2,%3}, [%4];"
        : "=r"(r[0]), "=r"(r[1]), "=r"(r[2]), "=r"(r[3]) : "r"(addr));
}
// fp16 inputs, fp32 accumulate (main term)
__device__ __forceinline__ void mma_f32(float* c, const uint32_t* a, const uint32_t* b) {
    asm volatile("mma.sync.aligned.m16n8k16.row.col.f32.f16.f16.f32 "
        "{%0,%1,%2,%3}, {%4,%5,%6,%7}, {%8,%9}, {%0,%1,%2,%3};"
        : "+f"(c[0]), "+f"(c[1]), "+f"(c[2]), "+f"(c[3])
        : "r"(a[0]), "r"(a[1]), "r"(a[2]), "r"(a[3]), "r"(b[0]), "r"(b[1]));
}
// fp16 inputs, fp16 accumulate (correction terms; possibly full-rate)
__device__ __forceinline__ void mma_f16(uint32_t* c, const uint32_t* a, const uint32_t* b) {
    asm volatile("mma.sync.aligned.m16n8k16.row.col.f16.f16.f16.f16 "
        "{%0,%1}, {%2,%3,%4,%5}, {%6,%7}, {%0,%1};"
        : "+r"(c[0]), "+r"(c[1])
        : "r"(a[0]), "r"(a[1]), "r"(a[2]), "r"(a[3]), "r"(b[0]), "r"(b[1]));
}
// fp32 -> fp16 hi + fp16 (lo * 2048)
__device__ __forceinline__ void split1(float v, __half& h, __half& l) {
    h = __float2half_rn(v);
    l = __float2half_rn((v - __half2float(h)) * LO_SCALE);
}

// ---------------- HMMA GEMM: C[M,N] = op(A)[M,K] @ W[N,K]^T + bias ----------------
// A fp32; split to fp16 hi / lo*2048 in-register at tile load. op(A)=relu(A*s+t) if BNRELU.
// W pre-split fp16 hi / lo*2048.
// Main term ahi*bhi in fp32 acc; corrections ahi*blo' + alo'*bhi in fp16 acc (scaled 2048).
// CTA 128x128, BK=32, 8 warps (warp tile 32x64), double-buffered smem.
// smem per stage: AH 0 | AL 10240 | BH 20480 | BL 30720 ; stage stride 40960; rows 80B.
// If STATS: per-column sum/sumsq of C accumulated into sums[0..N), sums[N..2N).
template<bool BNRELU, bool STATS>
__global__ void __launch_bounds__(256, 1)
mma_gemm_kernel(const float* __restrict__ A,
                const __half* __restrict__ Wh, const __half* __restrict__ Wl,
                const float* __restrict__ bias,
                const float* __restrict__ bnscale, const float* __restrict__ bnshift,
                float* __restrict__ C, float* __restrict__ sums, int N, int K)
{
    extern __shared__ char sm[];
    const uint32_t sbase = s2u(sm);
    const int tid  = threadIdx.x;
    const int lane = tid & 31, wid = tid >> 5;
    const int wm = wid & 3, wn = wid >> 2;          // 4 x 2 warp grid, tile 32x64
    const int m0 = blockIdx.y * 128, n0 = blockIdx.x * 128;

    const int grp = lane >> 3, gr = lane & 7;

    const uint32_t aHiAddr = sbase + (uint32_t)((wm * 32 + gr + (grp & 1) * 8) * 80 + (grp >> 1) * 16);
    const uint32_t aLoAddr = aHiAddr + 10240u;
    const uint32_t bAddr   = sbase + (grp < 2 ? 20480u : 30720u)
                           + (uint32_t)((wn * 64 + gr) * 80 + (grp & 1) * 16);

    const int arow = tid >> 1;
    const int akk  = (tid & 1) * 16;
    const uint32_t aStsOff = (uint32_t)(arow * 80 + (tid & 1) * 32);

    float    acc [2][8][4];
    uint32_t accH[2][8][2];
    #pragma unroll
    for (int i = 0; i < 2; i++)
        #pragma unroll
        for (int j = 0; j < 8; j++) {
            #pragma unroll
            for (int q = 0; q < 4; q++) acc[i][j][q] = 0.0f;
            accH[i][j][0] = 0u; accH[i][j][1] = 0u;
        }

    const int NT = K >> 5;
    float4 pa[4];

    auto ldgA = [&](int kc) {
        const float4* src = (const float4*)(A + (size_t)(m0 + arow) * K + kc + akk);
        #pragma unroll
        for (int i = 0; i < 4; i++) pa[i] = src[i];
    };
    auto cpB = [&](int kc, int stage) {
        const uint32_t so = (uint32_t)stage * 40960u;
        #pragma unroll
        for (int p = 0; p < 2; p++) {
            int i = tid + 256 * p; int row = i >> 2, sg = i & 3;
            uint32_t dh = sbase + so + 20480u + (uint32_t)(row * 80 + sg * 16);
            uint32_t dl = dh + 10240u;
            const __half* sh = Wh + (size_t)(n0 + row) * K + kc + sg * 8;
            const __half* sl = Wl + (size_t)(n0 + row) * K + kc + sg * 8;
            asm volatile("cp.async.cg.shared.global [%0], [%1], 16;" :: "r"(dh), "l"(sh));
            asm volatile("cp.async.cg.shared.global [%0], [%1], 16;" :: "r"(dl), "l"(sl));
        }
        asm volatile("cp.async.commit_group;" ::: "memory");
    };

    ldgA(0);
    cpB(0, 0);

    for (int kt = 0; kt < NT; kt++) {
        const int stage = kt & 1;
        const uint32_t so = (uint32_t)stage * 40960u;
        const int kc = kt << 5;

        __syncthreads();

        // ---- BN + fp16 hi/lo split + STS A(kt) ----
        {
            __half2 hp[8], lp[8];
            #pragma unroll
            for (int i = 0; i < 4; i++) {
                float4 v = pa[i];
                if (BNRELU) {
                    float4 s = ((const float4*)(bnscale + kc + akk))[i];
                    float4 t = ((const float4*)(bnshift + kc + akk))[i];
                    v.x = fmaxf(fmaf(v.x, s.x, t.x), 0.0f);
                    v.y = fmaxf(fmaf(v.y, s.y, t.y), 0.0f);
                    v.z = fmaxf(fmaf(v.z, s.z, t.z), 0.0f);
                    v.w = fmaxf(fmaf(v.w, s.w, t.w), 0.0f);
                }
                __half h0, h1, h2, h3, l0, l1, l2, l3;
                split1(v.x, h0, l0); split1(v.y, h1, l1);
                split1(v.z, h2, l2); split1(v.w, h3, l3);
                hp[2 * i]     = __halves2half2(h0, h1);
                hp[2 * i + 1] = __halves2half2(h2, h3);
                lp[2 * i]     = __halves2half2(l0, l1);
                lp[2 * i + 1] = __halves2half2(l2, l3);
            }
            char* dsth = sm + so + aStsOff;
            char* dstl = dsth + 10240;
            ((uint4*)dsth)[0] = ((uint4*)hp)[0];
            ((uint4*)dsth)[1] = ((uint4*)hp)[1];
            ((uint4*)dstl)[0] = ((uint4*)lp)[0];
            ((uint4*)dstl)[1] = ((uint4*)lp)[1];
        }

        if (kt + 1 < NT) {
            ldgA(kc + 32);
            cpB(kc + 32, stage ^ 1);
            asm volatile("cp.async.wait_group 1;" ::: "memory");
        } else {
            asm volatile("cp.async.wait_group 0;" ::: "memory");
        }
        __syncthreads();

        // ---- compute stage ----
        #pragma unroll
        for (int k16 = 0; k16 < 2; k16++) {
            const uint32_t kb = so + (uint32_t)(k16 * 32);
            uint32_t aHi[2][4], aLo[2][4];
            #pragma unroll
            for (int mt = 0; mt < 2; mt++) {
                ldsm_x4(aHi[mt], aHiAddr + kb + (uint32_t)(mt * 1280));
                ldsm_x4(aLo[mt], aLoAddr + kb + (uint32_t)(mt * 1280));
            }
            #pragma unroll
            for (int nt = 0; nt < 8; nt++) {
                uint32_t bb[4];   // bb[0..1]=Bhi frag, bb[2..3]=Blo' frag
                ldsm_x4(bb, bAddr + kb + (uint32_t)(nt * 640));
                // main term, fp32 acc
                mma_f32(acc[0][nt], aHi[0], bb + 0);
                mma_f32(acc[1][nt], aHi[1], bb + 0);
                // corrections (scaled by 2048), fp16 acc
                mma_f16(accH[0][nt], aHi[0], bb + 2);
                mma_f16(accH[1][nt], aHi[1], bb + 2);
                mma_f16(accH[0][nt], aLo[0], bb + 0);
                mma_f16(accH[1][nt], aLo[1], bb + 0);
            }
        }
    }

    // ---- epilogue: main + corrections/2048 + bias, stores, optional fused stats ----
    float* ssum = (float*)sm;   // [0..127]=col sum, [128..255]=col sumsq
    if (STATS) {
        __syncthreads();
        if (tid < 256) ssum[tid] = 0.0f;
        __syncthreads();
    }

    const int erow = m0 + wm * 32 + (lane >> 2);
    const int ecol = n0 + wn * 64 + ((lane & 3) << 1);
    #pragma unroll
    for (int nt = 0; nt < 8; nt++) {
        int c = ecol + nt * 8;
        float b0 = __ldg(&bias[c]), b1 = __ldg(&bias[c + 1]);
        float cs0 = 0.f, cq0 = 0.f, cs1 = 0.f, cq1 = 0.f;
        #pragma unroll
        for (int mt = 0; mt < 2; mt++) {
            int r = erow + mt * 16;
            float2 h01 = __half22float2(*(__half2*)&accH[mt][nt][0]);
            float2 h23 = __half22float2(*(__half2*)&accH[mt][nt][1]);
            float v0 = fmaf(h01.x, INV_LO_SCALE, acc[mt][nt][0]) + b0;
            float v1 = fmaf(h01.y, INV_LO_SCALE, acc[mt][nt][1]) + b1;
            float v2 = fmaf(h23.x, INV_LO_SCALE, acc[mt][nt][2]) + b0;
            float v3 = fmaf(h23.y, INV_LO_SCALE, acc[mt][nt][3]) + b1;
            C[(size_t)r * N + c]           = v0;
            C[(size_t)r * N + c + 1]       = v1;
            C[(size_t)(r + 8) * N + c]     = v2;
            C[(size_t)(r + 8) * N + c + 1] = v3;
            if (STATS) {
                cs0 += v0 + v2; cq0 = fmaf(v0, v0, fmaf(v2, v2, cq0));
                cs1 += v1 + v3; cq1 = fmaf(v1, v1, fmaf(v3, v3, cq1));
            }
        }
        if (STATS) {
            #pragma unroll
            for (int o = 4; o <= 16; o <<= 1) {
                cs0 += __shfl_xor_sync(0xffffffffu, cs0, o);
                cq0 += __shfl_xor_sync(0xffffffffu, cq0, o);
                cs1 += __shfl_xor_sync(0xffffffffu, cs1, o);
                cq1 += __shfl_xor_sync(0xffffffffu, cq1, o);
            }
            if (lane < 4) {
                int lc = wn * 64 + lane * 2 + nt * 8;
                atomicAdd(&ssum[lc],           cs0);
                atomicAdd(&ssum[128 + lc],     cq0);
                atomicAdd(&ssum[lc + 1],       cs1);
                atomicAdd(&ssum[128 + lc + 1], cq1);
            }
        }
    }
    if (STATS) {
        __syncthreads();
        if (tid < 128) {
            atomicAdd(&sums[n0 + tid],     ssum[tid]);
            atomicAdd(&sums[N + n0 + tid], ssum[128 + tid]);
        }
    }
}

#define GEMM_SMEM 81920

// ---------------- weight split fp32 -> fp16 hi / lo*2048 ----------------
__global__ void split_kernel(const float* __restrict__ x,
                             __half* __restrict__ hi,
                             __half* __restrict__ lo, int n4) {
    int i = blockIdx.x * blockDim.x + threadIdx.x;
    if (i >= n4) return;
    float4 v = ((const float4*)x)[i];
    __half h0, h1, h2, h3, l0, l1, l2, l3;
    split1(v.x, h0, l0); split1(v.y, h1, l1); split1(v.z, h2, l2); split1(v.w, h3, l3);
    ((__half2*)hi)[2 * (size_t)i]     = __halves2half2(h0, h1);
    ((__half2*)hi)[2 * (size_t)i + 1] = __halves2half2(h2, h3);
    ((__half2*)lo)[2 * (size_t)i]     = __halves2half2(l0, l1);
    ((__half2*)lo)[2 * (size_t)i + 1] = __halves2half2(l2, l3);
}

// ---------------- init: zero BN accumulators ----------------
__global__ void init_kernel() {
    int t = blockIdx.x * blockDim.x + threadIdx.x;
    if (t < 2 * D_L) g_sums_f[t] = 0.0f;
    if (t < 2 * D_G) g_sums_g[t] = 0.0f;
}

template<int C>
__global__ void bn_finalize_kernel(const float* __restrict__ sums,
                                   const float* __restrict__ gamma,
                                   const float* __restrict__ beta,
                                   float invM,
                                   float* __restrict__ scale,
                                   float* __restrict__ shift) {
    int c = threadIdx.x;
    if (c >= C) return;
    float m   = sums[c] * invM;
    float var = sums[C + c] * invM - m * m;
    float inv = rsqrtf(var + 1e-5f);
    float sc  = gamma[c] * inv;
    scale[c] = sc;
    shift[c] = beta[c] - m * sc;
}

// ---------------- L2 normalize + logit_scale ----------------
__global__ void l2norm_kernel(const float* __restrict__ G,
                              const float* __restrict__ ls,
                              float* __restrict__ out) {
    __shared__ float red[256];
    const int r = blockIdx.x, t = threadIdx.x;
    const float* g = G + (size_t)r * D_G;
    float s = 0.0f;
    for (int c = t; c < D_G; c += 256) { float v = g[c]; s = fmaf(v, v, s); }
    red[t] = s; __syncthreads();
    for (int o = 128; o > 0; o >>= 1) {
        if (t < o) red[t] += red[t + o];
        __syncthreads();
    }
    float inv = rsqrtf(red[0]);
    for (int c = t; c < D_G; c += 256)
        out[OFF_G + (size_t)r * D_G + c] = g[c] * inv;
    if (r == 0 && t == 0) out[OFF_LS] = expf(ls[0]);
}

// ---------------- fused fine epilogue: top-k select + gather + token mean ----------------
__global__ void fine_epilogue_kernel(const float* __restrict__ attn,
                                     const float* __restrict__ X2,
                                     float* __restrict__ outTop) {
    __shared__ float sv[256];
    __shared__ int   si[256];
    __shared__ int   sel[TOPK + 1];
    const int b = blockIdx.x, t = threadIdx.x;
    const float NEG = __int_as_float(0xff800000);

    float myv = (t < N_TOK - 1) ? attn[(size_t)b * (N_TOK - 1) + t] : NEG;
    if (t == 0) sel[0] = 0;
    __syncthreads();

    #pragma unroll 1
    for (int k = 0; k < TOPK; k++) {
        if (t < 256) { sv[t] = myv; si[t] = t; }
        __syncthreads();
        for (int o = 128; o > 0; o >>= 1) {
            if (t < o) {
                float v2 = sv[t + o]; int i2 = si[t + o];
                if (v2 > sv[t] || (v2 == sv[t] && i2 < si[t])) { sv[t] = v2; si[t] = i2; }
            }
            __syncthreads();
        }
        int win = si[0];
        if (t == 0)  sel[k + 1] = win + 1;
        if (t == win) myv = NEG;
        __syncthreads();
    }

    const float* xb = X2 + (size_t)b * N_TOK * D_L;
    float* ob = outTop + (size_t)b * (TOPK + 2) * D_L;
    #pragma unroll
    for (int j = 0; j < TOPK + 1; j++)
        ob[(size_t)j * D_L + t] = xb[(size_t)sel[j] * D_L + t];

    float s = 0.0f;
    #pragma unroll 4
    for (int n = 0; n < N_TOK; n++) s += xb[(size_t)n * D_L + t];
    ob[(size_t)(TOPK + 1) * D_L + t] = s * (1.0f / (float)N_TOK);
}

// ---------------- launch ----------------
extern "C" void kernel_launch(void* const* d_in, const int* in_sizes, int n_in,
                              void* d_out, int out_size)
{
    const float* image_features = (const float*)d_in[0];
    const float* fine_feat      = (const float*)d_in[1];
    const float* fine_attn      = (const float*)d_in[2];
    const float* logit_scale    = (const float*)d_in[3];
    const float* vpt_w1  = (const float*)d_in[4];
    const float* vpt_b1  = (const float*)d_in[5];
    const float* vpt_g1  = (const float*)d_in[6];
    const float* vpt_be1 = (const float*)d_in[7];
    const float* vpt_w2  = (const float*)d_in[8];
    const float* vpt_b2  = (const float*)d_in[9];
    const float* mid_w1  = (const float*)d_in[10];
    const float* mid_b1  = (const float*)d_in[11];
    const float* mid_g1  = (const float*)d_in[12];
    const float* mid_be1 = (const float*)d_in[13];
    const float* mid_w2  = (const float*)d_in[14];
    const float* mid_b2  = (const float*)d_in[15];
    float* out = (float*)d_out;

    __half *W1h, *W1l, *W2h, *W2l, *V1h, *V1l, *V2h, *V2l;
    float *Hf, *Hg, *G, *sf, *sg, *scf, *shf, *scg, *shg;
    cudaGetSymbolAddress((void**)&W1h, g_W1h); cudaGetSymbolAddress((void**)&W1l, g_W1l);
    cudaGetSymbolAddress((void**)&W2h, g_W2h); cudaGetSymbolAddress((void**)&W2l, g_W2l);
    cudaGetSymbolAddress((void**)&V1h, g_V1h); cudaGetSymbolAddress((void**)&V1l, g_V1l);
    cudaGetSymbolAddress((void**)&V2h, g_V2h); cudaGetSymbolAddress((void**)&V2l, g_V2l);
    cudaGetSymbolAddress((void**)&Hf,  g_Hf);  cudaGetSymbolAddress((void**)&Hg,  g_Hg);
    cudaGetSymbolAddress((void**)&G,   g_G);
    cudaGetSymbolAddress((void**)&sf,  g_sums_f);  cudaGetSymbolAddress((void**)&sg, g_sums_g);
    cudaGetSymbolAddress((void**)&scf, g_scale_f); cudaGetSymbolAddress((void**)&shf, g_shift_f);
    cudaGetSymbolAddress((void**)&scg, g_scale_g); cudaGetSymbolAddress((void**)&shg, g_shift_g);

    cudaFuncSetAttribute(mma_gemm_kernel<false, true>,  cudaFuncAttributeMaxDynamicSharedMemorySize, GEMM_SMEM);
    cudaFuncSetAttribute(mma_gemm_kernel<true,  false>, cudaFuncAttributeMaxDynamicSharedMemorySize, GEMM_SMEM);

    static cudaStream_t s1 = nullptr;
    static cudaEvent_t evFork = nullptr, evJoin = nullptr;
    if (s1 == nullptr) {
        cudaStreamCreateWithFlags(&s1, cudaStreamNonBlocking);
        cudaEventCreateWithFlags(&evFork, cudaEventDisableTiming);
        cudaEventCreateWithFlags(&evJoin, cudaEventDisableTiming);
    }

    auto blocks = [](int n4) { return (n4 + 255) / 256; };

    // launch #1: zero BN accumulators, fork point for global path
    init_kernel<<<8, 256>>>();
    cudaEventRecord(evFork, 0);
    cudaStreamWaitEvent(s1, evFork, 0);

    // ----- fine path (default stream) — order keeps ncu -s 5 on the fine GEMMs -----
    { int n4 = D_L * D_L / 4; split_kernel<<<blocks(n4), 256>>>(mid_w1, W1h, W1l, n4); }  // #2
    { int n4 = D_L * D_L / 4; split_kernel<<<blocks(n4), 256>>>(mid_w2, W2h, W2l, n4); }  // #3

    mma_gemm_kernel<false, true><<<dim3(D_L / 128, M_FINE / 128), 256, GEMM_SMEM>>>(      // #4
        fine_feat, W1h, W1l, mid_b1, nullptr, nullptr, Hf, sf, D_L, D_L);
    bn_finalize_kernel<D_L><<<1, D_L>>>(sf, mid_g1, mid_be1, 1.0f / (float)M_FINE, scf, shf); // #5
    mma_gemm_kernel<true, false><<<dim3(D_L / 128, M_FINE / 128), 256, GEMM_SMEM>>>(      // #6
        Hf, W2h, W2l, mid_b2, scf, shf, out + OFF_FINE, nullptr, D_L, D_L);

    fine_epilogue_kernel<<<B_SZ, 512>>>(fine_attn, out + OFF_FINE, out + OFF_TOP);

    // ----- global path (stream s1, overlaps fine path) -----
    { int n4 = D_G * D_L / 4; split_kernel<<<blocks(n4), 256, 0, s1>>>(vpt_w1, V1h, V1l, n4); }
    { int n4 = D_G * D_G / 4; split_kernel<<<blocks(n4), 256, 0, s1>>>(vpt_w2, V2h, V2l, n4); }

    mma_gemm_kernel<false, true><<<dim3(D_G / 128, B_SZ / 128), 256, GEMM_SMEM, s1>>>(
        image_features, V1h, V1l, vpt_b1, nullptr, nullptr, Hg, sg, D_G, D_L);
    bn_finalize_kernel<D_G><<<1, D_G, 0, s1>>>(sg, vpt_g1, vpt_be1, 1.0f / (float)B_SZ, scg, shg);
    mma_gemm_kernel<true, false><<<dim3(D_G / 128, B_SZ / 128), 256, GEMM_SMEM, s1>>>(
        Hg, V2h, V2l, vpt_b2, scg, shg, G, nullptr, D_G, D_G);
    l2norm_kernel<<<B_SZ, 256, 0, s1>>>(G, logit_scale, out);
    cudaEventRecord(evJoin, s1);

    // join
    cudaStreamWaitEvent(0, evJoin, 0);
}

// round 14
// speedup vs baseline: 1.5819x; 1.5819x over previous
#include <cuda_runtime.h>
#include <cuda_fp16.h>
#include <cstdint>
#include <math.h>

// ---------------- problem constants ----------------
#define B_SZ     256
#define N_TOK    197
#define D_L      512
#define D_G      768
#define M_FINE   (B_SZ * N_TOK)          // 50432
#define TOPK     5

#define OFF_G    0
#define OFF_LS   (B_SZ * D_G)                         // 196608
#define OFF_FINE (OFF_LS + 1)                         // 196609
#define OFF_TOP  (OFF_FINE + (size_t)M_FINE * D_L)

// ---------------- device scratch (weights single fp16; activations split in-kernel) ----------------
__device__ __align__(16) __half g_W1h[D_L * D_L];
__device__ __align__(16) __half g_W2h[D_L * D_L];
__device__ __align__(16) __half g_V1h[D_G * D_L];
__device__ __align__(16) __half g_V2h[D_G * D_G];
__device__ __align__(16) float g_Hf[(size_t)M_FINE * D_L];
__device__ __align__(16) float g_Hg[B_SZ * D_G];
__device__ __align__(16) float g_G [B_SZ * D_G];
__device__ __align__(16) float g_sums_f[2 * D_L];
__device__ __align__(16) float g_sums_g[2 * D_G];
__device__ __align__(16) float g_scale_f[D_L], g_shift_f[D_L];
__device__ __align__(16) float g_scale_g[D_G], g_shift_g[D_G];

// ---------------- helpers ----------------
__device__ __forceinline__ uint32_t s2u(const void* p) {
    uint32_t a;
    asm("{ .reg .u64 t; cvta.to.shared.u64 t, %1; cvt.u32.u64 %0, t; }" : "=r"(a) : "l"(p));
    return a;
}
__device__ __forceinline__ void ldsm_x4(uint32_t* r, uint32_t addr) {
    asm volatile("ldmatrix.sync.aligned.m8n8.x4.shared.b16 {%0,%1,%2,%3}, [%4];"
        : "=r"(r[0]), "=r"(r[1]), "=r"(r[2]), "=r"(r[3]) : "r"(addr));
}
__device__ __forceinline__ void mma_f32(float* c, const uint32_t* a, const uint32_t* b) {
    asm volatile("mma.sync.aligned.m16n8k16.row.col.f32.f16.f16.f32 "
        "{%0,%1,%2,%3}, {%4,%5,%6,%7}, {%8,%9}, {%0,%1,%2,%3};"
        : "+f"(c[0]), "+f"(c[1]), "+f"(c[2]), "+f"(c[3])
        : "r"(a[0]), "r"(a[1]), "r"(a[2]), "r"(a[3]), "r"(b[0]), "r"(b[1]));
}
// fp32 -> fp16 hi + fp16 lo (lo may be denormal; HMMA handles fp16 denormals)
__device__ __forceinline__ void split1(float v, __half& h, __half& l) {
    h = __float2half_rn(v);
    l = __float2half_rn(v - __half2float(h));
}

// ---------------- HMMA GEMM: C[M,N] = op(A)[M,K] @ W[N,K]^T + bias ----------------
// A fp32; split to fp16 hi/lo in-register at tile load. op(A)=relu(A*s+t) if BNRELU.
// W single fp16. 2-term: ahi*b + alo*b, both fp32 accumulate (same acc).
// CTA 128x128, BK=32, 8 warps (warp tile 32x64), double-buffered smem.
// smem per stage: AH 0 | AL 10240 | BH 20480 ; stage stride 30720; rows 80B.
// If STATS: per-column sum/sumsq of C accumulated into sums[0..N), sums[N..2N).
template<bool BNRELU, bool STATS>
__global__ void __launch_bounds__(256, 2)
mma_gemm_kernel(const float* __restrict__ A,
                const __half* __restrict__ Wh,
                const float* __restrict__ bias,
                const float* __restrict__ bnscale, const float* __restrict__ bnshift,
                float* __restrict__ C, float* __restrict__ sums, int N, int K)
{
    extern __shared__ char sm[];
    const uint32_t sbase = s2u(sm);
    const int tid  = threadIdx.x;
    const int lane = tid & 31, wid = tid >> 5;
    const int wm = wid & 3, wn = wid >> 2;          // 4 x 2 warp grid, tile 32x64
    const int m0 = blockIdx.y * 128, n0 = blockIdx.x * 128;

    const int grp = lane >> 3, gr = lane & 7;

    // A frag addresses (x4 = 16x16 tile)
    const uint32_t aHiAddr = sbase + (uint32_t)((wm * 32 + gr + (grp & 1) * 8) * 80 + (grp >> 1) * 16);
    const uint32_t aLoAddr = aHiAddr + 10240u;
    // B frag address: x4 packs TWO adjacent nt fragments (16 n-rows x k16)
    const uint32_t bAddr   = sbase + 20480u
                           + (uint32_t)((wn * 64 + (grp >> 1) * 8 + gr) * 80 + (grp & 1) * 16);

    const int arow = tid >> 1;
    const int akk  = (tid & 1) * 16;
    const uint32_t aStsOff = (uint32_t)(arow * 80 + (tid & 1) * 32);

    float acc[2][8][4];
    #pragma unroll
    for (int i = 0; i < 2; i++)
        #pragma unroll
        for (int j = 0; j < 8; j++)
            #pragma unroll
            for (int q = 0; q < 4; q++) acc[i][j][q] = 0.0f;

    const int NT = K >> 5;
    float4 pa[4];

    auto ldgA = [&](int kc) {
        const float4* src = (const float4*)(A + (size_t)(m0 + arow) * K + kc + akk);
        #pragma unroll
        for (int i = 0; i < 4; i++) pa[i] = src[i];
    };
    auto cpB = [&](int kc, int stage) {
        const uint32_t so = (uint32_t)stage * 30720u;
        #pragma unroll
        for (int p = 0; p < 2; p++) {
            int i = tid + 256 * p; int row = i >> 2, sg = i & 3;
            uint32_t dh = sbase + so + 20480u + (uint32_t)(row * 80 + sg * 16);
            const __half* sh = Wh + (size_t)(n0 + row) * K + kc + sg * 8;
            asm volatile("cp.async.cg.shared.global [%0], [%1], 16;" :: "r"(dh), "l"(sh));
        }
        asm volatile("cp.async.commit_group;" ::: "memory");
    };

    ldgA(0);
    cpB(0, 0);

    for (int kt = 0; kt < NT; kt++) {
        const int stage = kt & 1;
        const uint32_t so = (uint32_t)stage * 30720u;
        const int kc = kt << 5;

        __syncthreads();

        // ---- BN + fp16 hi/lo split + STS A(kt) ----
        {
            __half2 hp[8], lp[8];
            #pragma unroll
            for (int i = 0; i < 4; i++) {
                float4 v = pa[i];
                if (BNRELU) {
                    float4 s = ((const float4*)(bnscale + kc + akk))[i];
                    float4 t = ((const float4*)(bnshift + kc + akk))[i];
                    v.x = fmaxf(fmaf(v.x, s.x, t.x), 0.0f);
                    v.y = fmaxf(fmaf(v.y, s.y, t.y), 0.0f);
                    v.z = fmaxf(fmaf(v.z, s.z, t.z), 0.0f);
                    v.w = fmaxf(fmaf(v.w, s.w, t.w), 0.0f);
                }
                __half h0, h1, h2, h3, l0, l1, l2, l3;
                split1(v.x, h0, l0); split1(v.y, h1, l1);
                split1(v.z, h2, l2); split1(v.w, h3, l3);
                hp[2 * i]     = __halves2half2(h0, h1);
                hp[2 * i + 1] = __halves2half2(h2, h3);
                lp[2 * i]     = __halves2half2(l0, l1);
                lp[2 * i + 1] = __halves2half2(l2, l3);
            }
            char* dsth = sm + so + aStsOff;
            char* dstl = dsth + 10240;
            ((uint4*)dsth)[0] = ((uint4*)hp)[0];
            ((uint4*)dsth)[1] = ((uint4*)hp)[1];
            ((uint4*)dstl)[0] = ((uint4*)lp)[0];
            ((uint4*)dstl)[1] = ((uint4*)lp)[1];
        }

        if (kt + 1 < NT) {
            ldgA(kc + 32);
            cpB(kc + 32, stage ^ 1);
            asm volatile("cp.async.wait_group 1;" ::: "memory");
        } else {
            asm volatile("cp.async.wait_group 0;" ::: "memory");
        }
        __syncthreads();

        // ---- compute stage: per k16: 4 A-ldsm + 4 B-ldsm feed 32 MMAs ----
        #pragma unroll
        for (int k16 = 0; k16 < 2; k16++) {
            const uint32_t kb = so + (uint32_t)(k16 * 32);
            uint32_t aHi[2][4], aLo[2][4];
            #pragma unroll
            for (int mt = 0; mt < 2; mt++) {
                ldsm_x4(aHi[mt], aHiAddr + kb + (uint32_t)(mt * 1280));
                ldsm_x4(aLo[mt], aLoAddr + kb + (uint32_t)(mt * 1280));
            }
            #pragma unroll
            for (int ntp = 0; ntp < 4; ntp++) {
                uint32_t bb[4];   // bb[0..1] = nt=2*ntp frag, bb[2..3] = nt=2*ntp+1 frag
                ldsm_x4(bb, bAddr + kb + (uint32_t)(ntp * 1280));
                const int n0t = 2 * ntp, n1t = 2 * ntp + 1;
                // hi terms (acc reuse distance 4)
                mma_f32(acc[0][n0t], aHi[0], bb + 0);
                mma_f32(acc[1][n0t], aHi[1], bb + 0);
                mma_f32(acc[0][n1t], aHi[0], bb + 2);
                mma_f32(acc[1][n1t], aHi[1], bb + 2);
                // lo terms
                mma_f32(acc[0][n0t], aLo[0], bb + 0);
                mma_f32(acc[1][n0t], aLo[1], bb + 0);
                mma_f32(acc[0][n1t], aLo[0], bb + 2);
                mma_f32(acc[1][n1t], aLo[1], bb + 2);
            }
        }
    }

    // ---- epilogue: +bias, stores, optional fused column stats ----
    float* ssum = (float*)sm;   // [0..127]=col sum, [128..255]=col sumsq
    if (STATS) {
        __syncthreads();
        if (tid < 256) ssum[tid] = 0.0f;
        __syncthreads();
    }

    const int erow = m0 + wm * 32 + (lane >> 2);
    const int ecol = n0 + wn * 64 + ((lane & 3) << 1);
    #pragma unroll
    for (int nt = 0; nt < 8; nt++) {
        int c = ecol + nt * 8;
        float b0 = __ldg(&bias[c]), b1 = __ldg(&bias[c + 1]);
        float cs0 = 0.f, cq0 = 0.f, cs1 = 0.f, cq1 = 0.f;
        #pragma unroll
        for (int mt = 0; mt < 2; mt++) {
            int r = erow + mt * 16;
            float v0 = acc[mt][nt][0] + b0;
            float v1 = acc[mt][nt][1] + b1;
            float v2 = acc[mt][nt][2] + b0;
            float v3 = acc[mt][nt][3] + b1;
            C[(size_t)r * N + c]           = v0;
            C[(size_t)r * N + c + 1]       = v1;
            C[(size_t)(r + 8) * N + c]     = v2;
            C[(size_t)(r + 8) * N + c + 1] = v3;
            if (STATS) {
                cs0 += v0 + v2; cq0 = fmaf(v0, v0, fmaf(v2, v2, cq0));
                cs1 += v1 + v3; cq1 = fmaf(v1, v1, fmaf(v3, v3, cq1));
            }
        }
        if (STATS) {
            #pragma unroll
            for (int o = 4; o <= 16; o <<= 1) {
                cs0 += __shfl_xor_sync(0xffffffffu, cs0, o);
                cq0 += __shfl_xor_sync(0xffffffffu, cq0, o);
                cs1 += __shfl_xor_sync(0xffffffffu, cs1, o);
                cq1 += __shfl_xor_sync(0xffffffffu, cq1, o);
            }
            if (lane < 4) {
                int lc = wn * 64 + lane * 2 + nt * 8;
                atomicAdd(&ssum[lc],           cs0);
                atomicAdd(&ssum[128 + lc],     cq0);
                atomicAdd(&ssum[lc + 1],       cs1);
                atomicAdd(&ssum[128 + lc + 1], cq1);
            }
        }
    }
    if (STATS) {
        __syncthreads();
        if (tid < 128) {
            atomicAdd(&sums[n0 + tid],     ssum[tid]);
            atomicAdd(&sums[N + n0 + tid], ssum[128 + tid]);
        }
    }
}

#define GEMM_SMEM 61440

// ---------------- weight convert fp32 -> fp16 ----------------
__global__ void cvt_kernel(const float* __restrict__ x,
                           __half* __restrict__ hi, int n4) {
    int i = blockIdx.x * blockDim.x + threadIdx.x;
    if (i >= n4) return;
    float4 v = ((const float4*)x)[i];
    ((__half2*)hi)[2 * (size_t)i]     = __halves2half2(__float2half_rn(v.x), __float2half_rn(v.y));
    ((__half2*)hi)[2 * (size_t)i + 1] = __halves2half2(__float2half_rn(v.z), __float2half_rn(v.w));
}

// ---------------- init: zero BN accumulators ----------------
__global__ void init_kernel() {
    int t = blockIdx.x * blockDim.x + threadIdx.x;
    if (t < 2 * D_L) g_sums_f[t] = 0.0f;
    if (t < 2 * D_G) g_sums_g[t] = 0.0f;
}

template<int C>
__global__ void bn_finalize_kernel(const float* __restrict__ sums,
                                   const float* __restrict__ gamma,
                                   const float* __restrict__ beta,
                                   float invM,
                                   float* __restrict__ scale,
                                   float* __restrict__ shift) {
    int c = threadIdx.x;
    if (c >= C) return;
    float m   = sums[c] * invM;
    float var = sums[C + c] * invM - m * m;
    float inv = rsqrtf(var + 1e-5f);
    float sc  = gamma[c] * inv;
    scale[c] = sc;
    shift[c] = beta[c] - m * sc;
}

// ---------------- L2 normalize + logit_scale ----------------
__global__ void l2norm_kernel(const float* __restrict__ G,
                              const float* __restrict__ ls,
                              float* __restrict__ out) {
    __shared__ float red[256];
    const int r = blockIdx.x, t = threadIdx.x;
    const float* g = G + (size_t)r * D_G;
    float s = 0.0f;
    for (int c = t; c < D_G; c += 256) { float v = g[c]; s = fmaf(v, v, s); }
    red[t] = s; __syncthreads();
    for (int o = 128; o > 0; o >>= 1) {
        if (t < o) red[t] += red[t + o];
        __syncthreads();
    }
    float inv = rsqrtf(red[0]);
    for (int c = t; c < D_G; c += 256)
        out[OFF_G + (size_t)r * D_G + c] = g[c] * inv;
    if (r == 0 && t == 0) out[OFF_LS] = expf(ls[0]);
}

// ---------------- fused fine epilogue: top-k select + gather + token mean ----------------
__global__ void fine_epilogue_kernel(const float* __restrict__ attn,
                                     const float* __restrict__ X2,
                                     float* __restrict__ outTop) {
    __shared__ float sv[256];
    __shared__ int   si[256];
    __shared__ int   sel[TOPK + 1];
    const int b = blockIdx.x, t = threadIdx.x;
    const float NEG = __int_as_float(0xff800000);

    float myv = (t < N_TOK - 1) ? attn[(size_t)b * (N_TOK - 1) + t] : NEG;
    if (t == 0) sel[0] = 0;
    __syncthreads();

    #pragma unroll 1
    for (int k = 0; k < TOPK; k++) {
        if (t < 256) { sv[t] = myv; si[t] = t; }
        __syncthreads();
        for (int o = 128; o > 0; o >>= 1) {
            if (t < o) {
                float v2 = sv[t + o]; int i2 = si[t + o];
                if (v2 > sv[t] || (v2 == sv[t] && i2 < si[t])) { sv[t] = v2; si[t] = i2; }
            }
            __syncthreads();
        }
        int win = si[0];
        if (t == 0)  sel[k + 1] = win + 1;
        if (t == win) myv = NEG;
        __syncthreads();
    }

    const float* xb = X2 + (size_t)b * N_TOK * D_L;
    float* ob = outTop + (size_t)b * (TOPK + 2) * D_L;
    #pragma unroll
    for (int j = 0; j < TOPK + 1; j++)
        ob[(size_t)j * D_L + t] = xb[(size_t)sel[j] * D_L + t];

    float s = 0.0f;
    #pragma unroll 4
    for (int n = 0; n < N_TOK; n++) s += xb[(size_t)n * D_L + t];
    ob[(size_t)(TOPK + 1) * D_L + t] = s * (1.0f / (float)N_TOK);
}

// ---------------- launch ----------------
extern "C" void kernel_launch(void* const* d_in, const int* in_sizes, int n_in,
                              void* d_out, int out_size)
{
    const float* image_features = (const float*)d_in[0];
    const float* fine_feat      = (const float*)d_in[1];
    const float* fine_attn      = (const float*)d_in[2];
    const float* logit_scale    = (const float*)d_in[3];
    const float* vpt_w1  = (const float*)d_in[4];
    const float* vpt_b1  = (const float*)d_in[5];
    const float* vpt_g1  = (const float*)d_in[6];
    const float* vpt_be1 = (const float*)d_in[7];
    const float* vpt_w2  = (const float*)d_in[8];
    const float* vpt_b2  = (const float*)d_in[9];
    const float* mid_w1  = (const float*)d_in[10];
    const float* mid_b1  = (const float*)d_in[11];
    const float* mid_g1  = (const float*)d_in[12];
    const float* mid_be1 = (const float*)d_in[13];
    const float* mid_w2  = (const float*)d_in[14];
    const float* mid_b2  = (const float*)d_in[15];
    float* out = (float*)d_out;

    __half *W1h, *W2h, *V1h, *V2h;
    float *Hf, *Hg, *G, *sf, *sg, *scf, *shf, *scg, *shg;
    cudaGetSymbolAddress((void**)&W1h, g_W1h);
    cudaGetSymbolAddress((void**)&W2h, g_W2h);
    cudaGetSymbolAddress((void**)&V1h, g_V1h);
    cudaGetSymbolAddress((void**)&V2h, g_V2h);
    cudaGetSymbolAddress((void**)&Hf,  g_Hf);  cudaGetSymbolAddress((void**)&Hg,  g_Hg);
    cudaGetSymbolAddress((void**)&G,   g_G);
    cudaGetSymbolAddress((void**)&sf,  g_sums_f);  cudaGetSymbolAddress((void**)&sg, g_sums_g);
    cudaGetSymbolAddress((void**)&scf, g_scale_f); cudaGetSymbolAddress((void**)&shf, g_shift_f);
    cudaGetSymbolAddress((void**)&scg, g_scale_g); cudaGetSymbolAddress((void**)&shg, g_shift_g);

    cudaFuncSetAttribute(mma_gemm_kernel<false, true>,  cudaFuncAttributeMaxDynamicSharedMemorySize, GEMM_SMEM);
    cudaFuncSetAttribute(mma_gemm_kernel<true,  false>, cudaFuncAttributeMaxDynamicSharedMemorySize, GEMM_SMEM);

    static cudaStream_t s1 = nullptr;
    static cudaEvent_t evFork = nullptr, evJoin = nullptr;
    if (s1 == nullptr) {
        cudaStreamCreateWithFlags(&s1, cudaStreamNonBlocking);
        cudaEventCreateWithFlags(&evFork, cudaEventDisableTiming);
        cudaEventCreateWithFlags(&evJoin, cudaEventDisableTiming);
    }

    auto blocks = [](int n4) { return (n4 + 255) / 256; };

    // launch #1: zero BN accumulators, fork point for global path
    init_kernel<<<8, 256>>>();
    cudaEventRecord(evFork, 0);
    cudaStreamWaitEvent(s1, evFork, 0);

    // ----- fine path (default stream) — order keeps ncu -s 5 on the fine GEMMs -----
    { int n4 = D_L * D_L / 4; cvt_kernel<<<blocks(n4), 256>>>(mid_w1, W1h, n4); }  // #2
    { int n4 = D_L * D_L / 4; cvt_kernel<<<blocks(n4), 256>>>(mid_w2, W2h, n4); }  // #3

    mma_gemm_kernel<false, true><<<dim3(D_L / 128, M_FINE / 128), 256, GEMM_SMEM>>>(      // #4
        fine_feat, W1h, mid_b1, nullptr, nullptr, Hf, sf, D_L, D_L);
    bn_finalize_kernel<D_L><<<1, D_L>>>(sf, mid_g1, mid_be1, 1.0f / (float)M_FINE, scf, shf); // #5
    mma_gemm_kernel<true, false><<<dim3(D_L / 128, M_FINE / 128), 256, GEMM_SMEM>>>(      // #6
        Hf, W2h, mid_b2, scf, shf, out + OFF_FINE, nullptr, D_L, D_L);

    fine_epilogue_kernel<<<B_SZ, 512>>>(fine_attn, out + OFF_FINE, out + OFF_TOP);

    // ----- global path (stream s1, overlaps fine path) -----
    { int n4 = D_G * D_L / 4; cvt_kernel<<<blocks(n4), 256, 0, s1>>>(vpt_w1, V1h, n4); }
    { int n4 = D_G * D_G / 4; cvt_kernel<<<blocks(n4), 256, 0, s1>>>(vpt_w2, V2h, n4); }

    mma_gemm_kernel<false, true><<<dim3(D_G / 128, B_SZ / 128), 256, GEMM_SMEM, s1>>>(
        image_features, V1h, vpt_b1, nullptr, nullptr, Hg, sg, D_G, D_L);
    bn_finalize_kernel<D_G><<<1, D_G, 0, s1>>>(sg, vpt_g1, vpt_be1, 1.0f / (float)B_SZ, scg, shg);
    mma_gemm_kernel<true, false><<<dim3(D_G / 128, B_SZ / 128), 256, GEMM_SMEM, s1>>>(
        Hg, V2h, vpt_b2, scg, shg, G, nullptr, D_G, D_G);
    l2norm_kernel<<<B_SZ, 256, 0, s1>>>(G, logit_scale, out);
    cudaEventRecord(evJoin, s1);

    // join
    cudaStreamWaitEvent(0, evJoin, 0);
}

// round 15
// speedup vs baseline: 1.8471x; 1.1676x over previous
#include <cuda_runtime.h>
#include <cuda_fp16.h>
#include <cstdint>
#include <math.h>

// ---------------- problem constants ----------------
#define B_SZ     256
#define N_TOK    197
#define D_L      512
#define D_G      768
#define M_FINE   (B_SZ * N_TOK)          // 50432
#define TOPK     5

#define OFF_G    0
#define OFF_LS   (B_SZ * D_G)                         // 196608
#define OFF_FINE (OFF_LS + 1)                         // 196609
#define OFF_TOP  (OFF_FINE + (size_t)M_FINE * D_L)

// ---------------- device scratch (weights fp16; activations converted in-kernel) ----------------
__device__ __align__(16) __half g_W1h[D_L * D_L];
__device__ __align__(16) __half g_W2h[D_L * D_L];
__device__ __align__(16) __half g_V1h[D_G * D_L];
__device__ __align__(16) __half g_V2h[D_G * D_G];
__device__ __align__(16) float g_Hf[(size_t)M_FINE * D_L];
__device__ __align__(16) float g_Hg[B_SZ * D_G];
__device__ __align__(16) float g_G [B_SZ * D_G];
__device__ __align__(16) float g_sums_f[2 * D_L];
__device__ __align__(16) float g_sums_g[2 * D_G];
__device__ __align__(16) float g_scale_f[D_L], g_shift_f[D_L];
__device__ __align__(16) float g_scale_g[D_G], g_shift_g[D_G];

// ---------------- helpers ----------------
__device__ __forceinline__ uint32_t s2u(const void* p) {
    uint32_t a;
    asm("{ .reg .u64 t; cvta.to.shared.u64 t, %1; cvt.u32.u64 %0, t; }" : "=r"(a) : "l"(p));
    return a;
}
__device__ __forceinline__ void ldsm_x4(uint32_t* r, uint32_t addr) {
    asm volatile("ldmatrix.sync.aligned.m8n8.x4.shared.b16 {%0,%1,%2,%3}, [%4];"
        : "=r"(r[0]), "=r"(r[1]), "=r"(r[2]), "=r"(r[3]) : "r"(addr));
}
__device__ __forceinline__ void mma_f32(float* c, const uint32_t* a, const uint32_t* b) {
    asm volatile("mma.sync.aligned.m16n8k16.row.col.f32.f16.f16.f32 "
        "{%0,%1,%2,%3}, {%4,%5,%6,%7}, {%8,%9}, {%0,%1,%2,%3};"
        : "+f"(c[0]), "+f"(c[1]), "+f"(c[2]), "+f"(c[3])
        : "r"(a[0]), "r"(a[1]), "r"(a[2]), "r"(a[3]), "r"(b[0]), "r"(b[1]));
}

// ---------------- HMMA GEMM: C[M,N] = op(A)[M,K] @ W[N,K]^T + bias ----------------
// A fp32; converted to fp16 in-register at tile load. op(A)=relu(A*s+t) if BNRELU.
// W fp16. Single-term product, fp32 accumulate.
// CTA 128x128, BK=32, 8 warps (warp tile 32x64), double-buffered smem.
// smem per stage: AH 0 | BH 10240 ; stage stride 20480; rows 80B.
// If STATS: per-column sum/sumsq of C accumulated into sums[0..N), sums[N..2N).
template<bool BNRELU, bool STATS>
__global__ void __launch_bounds__(256, 2)
mma_gemm_kernel(const float* __restrict__ A,
                const __half* __restrict__ Wh,
                const float* __restrict__ bias,
                const float* __restrict__ bnscale, const float* __restrict__ bnshift,
                float* __restrict__ C, float* __restrict__ sums, int N, int K)
{
    extern __shared__ char sm[];
    const uint32_t sbase = s2u(sm);
    const int tid  = threadIdx.x;
    const int lane = tid & 31, wid = tid >> 5;
    const int wm = wid & 3, wn = wid >> 2;          // 4 x 2 warp grid, tile 32x64
    const int m0 = blockIdx.y * 128, n0 = blockIdx.x * 128;

    const int grp = lane >> 3, gr = lane & 7;

    // A frag address (x4 = 16x16 fp16 tile)
    const uint32_t aAddr = sbase + (uint32_t)((wm * 32 + gr + (grp & 1) * 8) * 80 + (grp >> 1) * 16);
    // B frag address: x4 packs TWO adjacent nt fragments (16 n-rows x k16)
    const uint32_t bAddr = sbase + 10240u
                         + (uint32_t)((wn * 64 + (grp >> 1) * 8 + gr) * 80 + (grp & 1) * 16);

    const int arow = tid >> 1;
    const int akk  = (tid & 1) * 16;
    const uint32_t aStsOff = (uint32_t)(arow * 80 + (tid & 1) * 32);

    float acc[2][8][4];
    #pragma unroll
    for (int i = 0; i < 2; i++)
        #pragma unroll
        for (int j = 0; j < 8; j++)
            #pragma unroll
            for (int q = 0; q < 4; q++) acc[i][j][q] = 0.0f;

    const int NT = K >> 5;
    float4 pa[4];

    auto ldgA = [&](int kc) {
        const float4* src = (const float4*)(A + (size_t)(m0 + arow) * K + kc + akk);
        #pragma unroll
        for (int i = 0; i < 4; i++) pa[i] = src[i];
    };
    auto cpB = [&](int kc, int stage) {
        const uint32_t so = (uint32_t)stage * 20480u;
        #pragma unroll
        for (int p = 0; p < 2; p++) {
            int i = tid + 256 * p; int row = i >> 2, sg = i & 3;
            uint32_t dh = sbase + so + 10240u + (uint32_t)(row * 80 + sg * 16);
            const __half* sh = Wh + (size_t)(n0 + row) * K + kc + sg * 8;
            asm volatile("cp.async.cg.shared.global [%0], [%1], 16;" :: "r"(dh), "l"(sh));
        }
        asm volatile("cp.async.commit_group;" ::: "memory");
    };

    ldgA(0);
    cpB(0, 0);

    for (int kt = 0; kt < NT; kt++) {
        const int stage = kt & 1;
        const uint32_t so = (uint32_t)stage * 20480u;
        const int kc = kt << 5;

        __syncthreads();

        // ---- BN + fp16 convert + STS A(kt) ----
        {
            __half2 hp[8];
            #pragma unroll
            for (int i = 0; i < 4; i++) {
                float4 v = pa[i];
                if (BNRELU) {
                    float4 s = ((const float4*)(bnscale + kc + akk))[i];
                    float4 t = ((const float4*)(bnshift + kc + akk))[i];
                    v.x = fmaxf(fmaf(v.x, s.x, t.x), 0.0f);
                    v.y = fmaxf(fmaf(v.y, s.y, t.y), 0.0f);
                    v.z = fmaxf(fmaf(v.z, s.z, t.z), 0.0f);
                    v.w = fmaxf(fmaf(v.w, s.w, t.w), 0.0f);
                }
                hp[2 * i]     = __halves2half2(__float2half_rn(v.x), __float2half_rn(v.y));
                hp[2 * i + 1] = __halves2half2(__float2half_rn(v.z), __float2half_rn(v.w));
            }
            char* dsth = sm + so + aStsOff;
            ((uint4*)dsth)[0] = ((uint4*)hp)[0];
            ((uint4*)dsth)[1] = ((uint4*)hp)[1];
        }

        if (kt + 1 < NT) {
            ldgA(kc + 32);
            cpB(kc + 32, stage ^ 1);
            asm volatile("cp.async.wait_group 1;" ::: "memory");
        } else {
            asm volatile("cp.async.wait_group 0;" ::: "memory");
        }
        __syncthreads();

        // ---- compute stage: per k16: 2 A-ldsm + 4 B-ldsm feed 16 MMAs ----
        #pragma unroll
        for (int k16 = 0; k16 < 2; k16++) {
            const uint32_t kb = so + (uint32_t)(k16 * 32);
            uint32_t aF[2][4];
            #pragma unroll
            for (int mt = 0; mt < 2; mt++)
                ldsm_x4(aF[mt], aAddr + kb + (uint32_t)(mt * 1280));
            #pragma unroll
            for (int ntp = 0; ntp < 4; ntp++) {
                uint32_t bb[4];   // bb[0..1] = nt=2*ntp frag, bb[2..3] = nt=2*ntp+1 frag
                ldsm_x4(bb, bAddr + kb + (uint32_t)(ntp * 1280));
                const int n0t = 2 * ntp, n1t = 2 * ntp + 1;
                mma_f32(acc[0][n0t], aF[0], bb + 0);
                mma_f32(acc[1][n0t], aF[1], bb + 0);
                mma_f32(acc[0][n1t], aF[0], bb + 2);
                mma_f32(acc[1][n1t], aF[1], bb + 2);
            }
        }
    }

    // ---- epilogue: +bias, stores, optional fused column stats ----
    float* ssum = (float*)sm;   // [0..127]=col sum, [128..255]=col sumsq
    if (STATS) {
        __syncthreads();
        if (tid < 256) ssum[tid] = 0.0f;
        __syncthreads();
    }

    const int erow = m0 + wm * 32 + (lane >> 2);
    const int ecol = n0 + wn * 64 + ((lane & 3) << 1);
    #pragma unroll
    for (int nt = 0; nt < 8; nt++) {
        int c = ecol + nt * 8;
        float b0 = __ldg(&bias[c]), b1 = __ldg(&bias[c + 1]);
        float cs0 = 0.f, cq0 = 0.f, cs1 = 0.f, cq1 = 0.f;
        #pragma unroll
        for (int mt = 0; mt < 2; mt++) {
            int r = erow + mt * 16;
            float v0 = acc[mt][nt][0] + b0;
            float v1 = acc[mt][nt][1] + b1;
            float v2 = acc[mt][nt][2] + b0;
            float v3 = acc[mt][nt][3] + b1;
            C[(size_t)r * N + c]           = v0;
            C[(size_t)r * N + c + 1]       = v1;
            C[(size_t)(r + 8) * N + c]     = v2;
            C[(size_t)(r + 8) * N + c + 1] = v3;
            if (STATS) {
                cs0 += v0 + v2; cq0 = fmaf(v0, v0, fmaf(v2, v2, cq0));
                cs1 += v1 + v3; cq1 = fmaf(v1, v1, fmaf(v3, v3, cq1));
            }
        }
        if (STATS) {
            #pragma unroll
            for (int o = 4; o <= 16; o <<= 1) {
                cs0 += __shfl_xor_sync(0xffffffffu, cs0, o);
                cq0 += __shfl_xor_sync(0xffffffffu, cq0, o);
                cs1 += __shfl_xor_sync(0xffffffffu, cs1, o);
                cq1 += __shfl_xor_sync(0xffffffffu, cq1, o);
            }
            if (lane < 4) {
                int lc = wn * 64 + lane * 2 + nt * 8;
                atomicAdd(&ssum[lc],           cs0);
                atomicAdd(&ssum[128 + lc],     cq0);
                atomicAdd(&ssum[lc + 1],       cs1);
                atomicAdd(&ssum[128 + lc + 1], cq1);
            }
        }
    }
    if (STATS) {
        __syncthreads();
        if (tid < 128) {
            atomicAdd(&sums[n0 + tid],     ssum[tid]);
            atomicAdd(&sums[N + n0 + tid], ssum[128 + tid]);
        }
    }
}

#define GEMM_SMEM 40960

// ---------------- weight convert fp32 -> fp16 ----------------
__global__ void cvt_kernel(const float* __restrict__ x,
                           __half* __restrict__ hi, int n4) {
    int i = blockIdx.x * blockDim.x + threadIdx.x;
    if (i >= n4) return;
    float4 v = ((const float4*)x)[i];
    ((__half2*)hi)[2 * (size_t)i]     = __halves2half2(__float2half_rn(v.x), __float2half_rn(v.y));
    ((__half2*)hi)[2 * (size_t)i + 1] = __halves2half2(__float2half_rn(v.z), __float2half_rn(v.w));
}

// ---------------- init: zero BN accumulators ----------------
__global__ void init_kernel() {
    int t = blockIdx.x * blockDim.x + threadIdx.x;
    if (t < 2 * D_L) g_sums_f[t] = 0.0f;
    if (t < 2 * D_G) g_sums_g[t] = 0.0f;
}

template<int C>
__global__ void bn_finalize_kernel(const float* __restrict__ sums,
                                   const float* __restrict__ gamma,
                                   const float* __restrict__ beta,
                                   float invM,
                                   float* __restrict__ scale,
                                   float* __restrict__ shift) {
    int c = threadIdx.x;
    if (c >= C) return;
    float m   = sums[c] * invM;
    float var = sums[C + c] * invM - m * m;
    float inv = rsqrtf(var + 1e-5f);
    float sc  = gamma[c] * inv;
    scale[c] = sc;
    shift[c] = beta[c] - m * sc;
}

// ---------------- L2 normalize + logit_scale ----------------
__global__ void l2norm_kernel(const float* __restrict__ G,
                              const float* __restrict__ ls,
                              float* __restrict__ out) {
    __shared__ float red[256];
    const int r = blockIdx.x, t = threadIdx.x;
    const float* g = G + (size_t)r * D_G;
    float s = 0.0f;
    for (int c = t; c < D_G; c += 256) { float v = g[c]; s = fmaf(v, v, s); }
    red[t] = s; __syncthreads();
    for (int o = 128; o > 0; o >>= 1) {
        if (t < o) red[t] += red[t + o];
        __syncthreads();
    }
    float inv = rsqrtf(red[0]);
    for (int c = t; c < D_G; c += 256)
        out[OFF_G + (size_t)r * D_G + c] = g[c] * inv;
    if (r == 0 && t == 0) out[OFF_LS] = expf(ls[0]);
}

// ---------------- fused fine epilogue: top-k select + gather + token mean ----------------
__global__ void fine_epilogue_kernel(const float* __restrict__ attn,
                                     const float* __restrict__ X2,
                                     float* __restrict__ outTop) {
    __shared__ float sv[256];
    __shared__ int   si[256];
    __shared__ int   sel[TOPK + 1];
    const int b = blockIdx.x, t = threadIdx.x;
    const float NEG = __int_as_float(0xff800000);

    float myv = (t < N_TOK - 1) ? attn[(size_t)b * (N_TOK - 1) + t] : NEG;
    if (t == 0) sel[0] = 0;
    __syncthreads();

    #pragma unroll 1
    for (int k = 0; k < TOPK; k++) {
        if (t < 256) { sv[t] = myv; si[t] = t; }
        __syncthreads();
        for (int o = 128; o > 0; o >>= 1) {
            if (t < o) {
                float v2 = sv[t + o]; int i2 = si[t + o];
                if (v2 > sv[t] || (v2 == sv[t] && i2 < si[t])) { sv[t] = v2; si[t] = i2; }
            }
            __syncthreads();
        }
        int win = si[0];
        if (t == 0)  sel[k + 1] = win + 1;
        if (t == win) myv = NEG;
        __syncthreads();
    }

    const float* xb = X2 + (size_t)b * N_TOK * D_L;
    float* ob = outTop + (size_t)b * (TOPK + 2) * D_L;
    #pragma unroll
    for (int j = 0; j < TOPK + 1; j++)
        ob[(size_t)j * D_L + t] = xb[(size_t)sel[j] * D_L + t];

    float s = 0.0f;
    #pragma unroll 4
    for (int n = 0; n < N_TOK; n++) s += xb[(size_t)n * D_L + t];
    ob[(size_t)(TOPK + 1) * D_L + t] = s * (1.0f / (float)N_TOK);
}

// ---------------- launch ----------------
extern "C" void kernel_launch(void* const* d_in, const int* in_sizes, int n_in,
                              void* d_out, int out_size)
{
    const float* image_features = (const float*)d_in[0];
    const float* fine_feat      = (const float*)d_in[1];
    const float* fine_attn      = (const float*)d_in[2];
    const float* logit_scale    = (const float*)d_in[3];
    const float* vpt_w1  = (const float*)d_in[4];
    const float* vpt_b1  = (const float*)d_in[5];
    const float* vpt_g1  = (const float*)d_in[6];
    const float* vpt_be1 = (const float*)d_in[7];
    const float* vpt_w2  = (const float*)d_in[8];
    const float* vpt_b2  = (const float*)d_in[9];
    const float* mid_w1  = (const float*)d_in[10];
    const float* mid_b1  = (const float*)d_in[11];
    const float* mid_g1  = (const float*)d_in[12];
    const float* mid_be1 = (const float*)d_in[13];
    const float* mid_w2  = (const float*)d_in[14];
    const float* mid_b2  = (const float*)d_in[15];
    float* out = (float*)d_out;

    __half *W1h, *W2h, *V1h, *V2h;
    float *Hf, *Hg, *G, *sf, *sg, *scf, *shf, *scg, *shg;
    cudaGetSymbolAddress((void**)&W1h, g_W1h);
    cudaGetSymbolAddress((void**)&W2h, g_W2h);
    cudaGetSymbolAddress((void**)&V1h, g_V1h);
    cudaGetSymbolAddress((void**)&V2h, g_V2h);
    cudaGetSymbolAddress((void**)&Hf,  g_Hf);  cudaGetSymbolAddress((void**)&Hg,  g_Hg);
    cudaGetSymbolAddress((void**)&G,   g_G);
    cudaGetSymbolAddress((void**)&sf,  g_sums_f);  cudaGetSymbolAddress((void**)&sg, g_sums_g);
    cudaGetSymbolAddress((void**)&scf, g_scale_f); cudaGetSymbolAddress((void**)&shf, g_shift_f);
    cudaGetSymbolAddress((void**)&scg, g_scale_g); cudaGetSymbolAddress((void**)&shg, g_shift_g);

    cudaFuncSetAttribute(mma_gemm_kernel<false, true>,  cudaFuncAttributeMaxDynamicSharedMemorySize, GEMM_SMEM);
    cudaFuncSetAttribute(mma_gemm_kernel<true,  false>, cudaFuncAttributeMaxDynamicSharedMemorySize, GEMM_SMEM);

    static cudaStream_t s1 = nullptr;
    static cudaEvent_t evFork = nullptr, evJoin = nullptr;
    if (s1 == nullptr) {
        cudaStreamCreateWithFlags(&s1, cudaStreamNonBlocking);
        cudaEventCreateWithFlags(&evFork, cudaEventDisableTiming);
        cudaEventCreateWithFlags(&evJoin, cudaEventDisableTiming);
    }

    auto blocks = [](int n4) { return (n4 + 255) / 256; };

    // launch #1: zero BN accumulators, fork point for global path
    init_kernel<<<8, 256>>>();
    cudaEventRecord(evFork, 0);
    cudaStreamWaitEvent(s1, evFork, 0);

    // ----- fine path (default stream) — order keeps ncu -s 5 on the fine GEMMs -----
    { int n4 = D_L * D_L / 4; cvt_kernel<<<blocks(n4), 256>>>(mid_w1, W1h, n4); }  // #2
    { int n4 = D_L * D_L / 4; cvt_kernel<<<blocks(n4), 256>>>(mid_w2, W2h, n4); }  // #3

    mma_gemm_kernel<false, true><<<dim3(D_L / 128, M_FINE / 128), 256, GEMM_SMEM>>>(      // #4
        fine_feat, W1h, mid_b1, nullptr, nullptr, Hf, sf, D_L, D_L);
    bn_finalize_kernel<D_L><<<1, D_L>>>(sf, mid_g1, mid_be1, 1.0f / (float)M_FINE, scf, shf); // #5
    mma_gemm_kernel<true, false><<<dim3(D_L / 128, M_FINE / 128), 256, GEMM_SMEM>>>(      // #6
        Hf, W2h, mid_b2, scf, shf, out + OFF_FINE, nullptr, D_L, D_L);

    fine_epilogue_kernel<<<B_SZ, 512>>>(fine_attn, out + OFF_FINE, out + OFF_TOP);

    // ----- global path (stream s1, overlaps fine path) -----
    { int n4 = D_G * D_L / 4; cvt_kernel<<<blocks(n4), 256, 0, s1>>>(vpt_w1, V1h, n4); }
    { int n4 = D_G * D_G / 4; cvt_kernel<<<blocks(n4), 256, 0, s1>>>(vpt_w2, V2h, n4); }

    mma_gemm_kernel<false, true><<<dim3(D_G / 128, B_SZ / 128), 256, GEMM_SMEM, s1>>>(
        image_features, V1h, vpt_b1, nullptr, nullptr, Hg, sg, D_G, D_L);
    bn_finalize_kernel<D_G><<<1, D_G, 0, s1>>>(sg, vpt_g1, vpt_be1, 1.0f / (float)B_SZ, scg, shg);
    mma_gemm_kernel<true, false><<<dim3(D_G / 128, B_SZ / 128), 256, GEMM_SMEM, s1>>>(
        Hg, V2h, vpt_b2, scg, shg, G, nullptr, D_G, D_G);
    l2norm_kernel<<<B_SZ, 256, 0, s1>>>(G, logit_scale, out);
    cudaEventRecord(evJoin, s1);

    // join
    cudaStreamWaitEvent(0, evJoin, 0);
}

// round 16
// speedup vs baseline: 2.1304x; 1.1534x over previous
#include <cuda_runtime.h>
#include <cuda_fp16.h>
#include <cstdint>
#include <math.h>

// ---------------- problem constants ----------------
#define B_SZ     256
#define N_TOK    197
#define D_L      512
#define D_G      768
#define M_FINE   (B_SZ * N_TOK)          // 50432
#define TOPK     5

#define OFF_G    0
#define OFF_LS   (B_SZ * D_G)                         // 196608
#define OFF_FINE (OFF_LS + 1)                         // 196609
#define OFF_TOP  (OFF_FINE + (size_t)M_FINE * D_L)

// ---------------- device scratch (all-fp16 GEMM operands) ----------------
__device__ __align__(16) __half g_A1h[(size_t)M_FINE * D_L];   // fine A (then reused for A2)
__device__ __align__(16) __half g_Hfh[(size_t)M_FINE * D_L];   // fine hidden (fp16)
__device__ __align__(16) __half g_W1h[D_L * D_L];
__device__ __align__(16) __half g_W2h[D_L * D_L];
__device__ __align__(16) __half g_V1h[D_G * D_L];
__device__ __align__(16) __half g_V2h[D_G * D_G];
__device__ __align__(16) __half g_gAh[B_SZ * D_G];             // global A (reused for A2)
__device__ __align__(16) __half g_Hgh[B_SZ * D_G];
__device__ __align__(16) float g_G [B_SZ * D_G];
__device__ __align__(16) float g_sums_f[2 * D_L];
__device__ __align__(16) float g_sums_g[2 * D_G];
__device__ __align__(16) float g_scale_f[D_L], g_shift_f[D_L];
__device__ __align__(16) float g_scale_g[D_G], g_shift_g[D_G];

// ---------------- helpers ----------------
__device__ __forceinline__ uint32_t s2u(const void* p) {
    uint32_t a;
    asm("{ .reg .u64 t; cvta.to.shared.u64 t, %1; cvt.u32.u64 %0, t; }" : "=r"(a) : "l"(p));
    return a;
}
__device__ __forceinline__ void ldsm_x4(uint32_t* r, uint32_t addr) {
    asm volatile("ldmatrix.sync.aligned.m8n8.x4.shared.b16 {%0,%1,%2,%3}, [%4];"
        : "=r"(r[0]), "=r"(r[1]), "=r"(r[2]), "=r"(r[3]) : "r"(addr));
}
__device__ __forceinline__ void mma_f32(float* c, const uint32_t* a, const uint32_t* b) {
    asm volatile("mma.sync.aligned.m16n8k16.row.col.f32.f16.f16.f32 "
        "{%0,%1,%2,%3}, {%4,%5,%6,%7}, {%8,%9}, {%0,%1,%2,%3};"
        : "+f"(c[0]), "+f"(c[1]), "+f"(c[2]), "+f"(c[3])
        : "r"(a[0]), "r"(a[1]), "r"(a[2]), "r"(a[3]), "r"(b[0]), "r"(b[1]));
}

// ---------------- pure-fp16 HMMA GEMM: C = A[M,K] @ B[N,K]^T + bias ----------------
// Both operands fp16 in global, loaded via cp.async (3-stage pipeline).
// CTA 128x128, BK=32, 4 warps (warp tile 64x64).
// smem per stage: A 10240 B | B 10240 B ; stage stride 20480; rows padded to 80 B.
// STATS=true : writes Ch (fp16) + per-column sum/sumsq into sums[0..N),[N..2N).
// STATS=false: writes Cf (fp32).
template<bool STATS>
__global__ void __launch_bounds__(128, 2)
hgemm_kernel(const __half* __restrict__ A, const __half* __restrict__ B,
             const float* __restrict__ bias,
             __half* __restrict__ Ch, float* __restrict__ Cf,
             float* __restrict__ sums, int N, int K)
{
    extern __shared__ char sm[];
    const uint32_t sbase = s2u(sm);
    const int tid  = threadIdx.x;
    const int lane = tid & 31, wid = tid >> 5;
    const int wm = wid & 1, wn = wid >> 1;          // 2 x 2 warp grid, warp tile 64x64
    const int m0 = blockIdx.y * 128, n0 = blockIdx.x * 128;
    const int grp = lane >> 3, gr = lane & 7;

    // A frag address (x4 = 16x16 fp16 tile)
    const uint32_t aAddr = sbase + (uint32_t)((wm * 64 + gr + (grp & 1) * 8) * 80 + (grp >> 1) * 16);
    // B frag address: x4 packs TWO adjacent nt fragments
    const uint32_t bAddr = sbase + 10240u
                         + (uint32_t)((wn * 64 + (grp >> 1) * 8 + gr) * 80 + (grp & 1) * 16);

    float acc[4][8][4];
    #pragma unroll
    for (int i = 0; i < 4; i++)
        #pragma unroll
        for (int j = 0; j < 8; j++)
            #pragma unroll
            for (int q = 0; q < 4; q++) acc[i][j][q] = 0.0f;

    const int NT = K >> 5;

    auto cp_stage = [&](int kc, int st) {
        const uint32_t so = (uint32_t)st * 20480u;
        #pragma unroll
        for (int p = 0; p < 4; p++) {
            int i = tid + 128 * p; int row = i >> 2, sg = i & 3;
            uint32_t da = sbase + so + (uint32_t)(row * 80 + sg * 16);
            const __half* sa = A + (size_t)(m0 + row) * K + kc + sg * 8;
            asm volatile("cp.async.cg.shared.global [%0], [%1], 16;" :: "r"(da), "l"(sa));
            const __half* sb = B + (size_t)(n0 + row) * K + kc + sg * 8;
            asm volatile("cp.async.cg.shared.global [%0], [%1], 16;" :: "r"(da + 10240u), "l"(sb));
        }
        asm volatile("cp.async.commit_group;" ::: "memory");
    };

    cp_stage(0, 0);
    cp_stage(32, 1);

    for (int kt = 0; kt < NT; kt++) {
        if (kt + 1 < NT) { asm volatile("cp.async.wait_group 1;" ::: "memory"); }
        else             { asm volatile("cp.async.wait_group 0;" ::: "memory"); }
        __syncthreads();
        if (kt + 2 < NT) cp_stage((kt + 2) << 5, (kt + 2) % 3);

        const uint32_t so = (uint32_t)(kt % 3) * 20480u;
        #pragma unroll
        for (int k16 = 0; k16 < 2; k16++) {
            const uint32_t kb = so + (uint32_t)(k16 * 32);
            uint32_t aF[4][4];
            #pragma unroll
            for (int mt = 0; mt < 4; mt++)
                ldsm_x4(aF[mt], aAddr + kb + (uint32_t)(mt * 1280));
            #pragma unroll
            for (int ntp = 0; ntp < 4; ntp++) {
                uint32_t bb[4];
                ldsm_x4(bb, bAddr + kb + (uint32_t)(ntp * 1280));
                const int n0t = 2 * ntp, n1t = 2 * ntp + 1;
                #pragma unroll
                for (int mt = 0; mt < 4; mt++) mma_f32(acc[mt][n0t], aF[mt], bb + 0);
                #pragma unroll
                for (int mt = 0; mt < 4; mt++) mma_f32(acc[mt][n1t], aF[mt], bb + 2);
            }
        }
    }

    // ---- epilogue ----
    float* ssum = (float*)sm;   // [0..127]=col sum, [128..255]=col sumsq
    if (STATS) {
        __syncthreads();
        if (tid < 128) { ssum[tid] = 0.0f; ssum[128 + tid] = 0.0f; }
        __syncthreads();
    }

    const int erow = m0 + wm * 64 + (lane >> 2);
    const int ecol = n0 + wn * 64 + ((lane & 3) << 1);
    #pragma unroll
    for (int nt = 0; nt < 8; nt++) {
        int c = ecol + nt * 8;
        float b0 = __ldg(&bias[c]), b1 = __ldg(&bias[c + 1]);
        float cs0 = 0.f, cq0 = 0.f, cs1 = 0.f, cq1 = 0.f;
        #pragma unroll
        for (int mt = 0; mt < 4; mt++) {
            int r = erow + mt * 16;
            float v0 = acc[mt][nt][0] + b0;
            float v1 = acc[mt][nt][1] + b1;
            float v2 = acc[mt][nt][2] + b0;
            float v3 = acc[mt][nt][3] + b1;
            if (STATS) {
                Ch[(size_t)r * N + c]           = __float2half_rn(v0);
                Ch[(size_t)r * N + c + 1]       = __float2half_rn(v1);
                Ch[(size_t)(r + 8) * N + c]     = __float2half_rn(v2);
                Ch[(size_t)(r + 8) * N + c + 1] = __float2half_rn(v3);
                cs0 += v0 + v2; cq0 = fmaf(v0, v0, fmaf(v2, v2, cq0));
                cs1 += v1 + v3; cq1 = fmaf(v1, v1, fmaf(v3, v3, cq1));
            } else {
                Cf[(size_t)r * N + c]           = v0;
                Cf[(size_t)r * N + c + 1]       = v1;
                Cf[(size_t)(r + 8) * N + c]     = v2;
                Cf[(size_t)(r + 8) * N + c + 1] = v3;
            }
        }
        if (STATS) {
            #pragma unroll
            for (int o = 4; o <= 16; o <<= 1) {
                cs0 += __shfl_xor_sync(0xffffffffu, cs0, o);
                cq0 += __shfl_xor_sync(0xffffffffu, cq0, o);
                cs1 += __shfl_xor_sync(0xffffffffu, cs1, o);
                cq1 += __shfl_xor_sync(0xffffffffu, cq1, o);
            }
            if (lane < 4) {
                int lc = wn * 64 + lane * 2 + nt * 8;
                atomicAdd(&ssum[lc],           cs0);
                atomicAdd(&ssum[128 + lc],     cq0);
                atomicAdd(&ssum[lc + 1],       cs1);
                atomicAdd(&ssum[128 + lc + 1], cq1);
            }
        }
    }
    if (STATS) {
        __syncthreads();
        if (tid < 128) {
            atomicAdd(&sums[n0 + tid],     ssum[tid]);
            atomicAdd(&sums[N + n0 + tid], ssum[128 + tid]);
        }
    }
}

#define GEMM_SMEM 61440

// ---------------- fp32 -> fp16 convert ----------------
__global__ void cvt_kernel(const float* __restrict__ x,
                           __half* __restrict__ o, int n4) {
    int i = blockIdx.x * blockDim.x + threadIdx.x;
    if (i >= n4) return;
    float4 v = ((const float4*)x)[i];
    ((__half2*)o)[2 * (size_t)i]     = __floats2half2_rn(v.x, v.y);
    ((__half2*)o)[2 * (size_t)i + 1] = __floats2half2_rn(v.z, v.w);
}

// ---------------- BN + ReLU on fp16 hidden -> fp16 activations ----------------
// x layout [M, C] row-major; processes 8 halves (8 consecutive channels) per thread.
__global__ void bnrelu_kernel(const __half* __restrict__ h,
                              const float* __restrict__ sc, const float* __restrict__ sh,
                              __half* __restrict__ o, int n8, int Cd8) {
    int i = blockIdx.x * blockDim.x + threadIdx.x;
    if (i >= n8) return;
    uint4 v = ((const uint4*)h)[i];
    int c8 = i % Cd8;
    float4 s0 = ((const float4*)sc)[c8 * 2], s1 = ((const float4*)sc)[c8 * 2 + 1];
    float4 t0 = ((const float4*)sh)[c8 * 2], t1 = ((const float4*)sh)[c8 * 2 + 1];
    __half2* hv = (__half2*)&v;
    uint4 out;
    __half2* ov = (__half2*)&out;
    float2 f;
    f = __half22float2(hv[0]);
    ov[0] = __floats2half2_rn(fmaxf(fmaf(f.x, s0.x, t0.x), 0.f), fmaxf(fmaf(f.y, s0.y, t0.y), 0.f));
    f = __half22float2(hv[1]);
    ov[1] = __floats2half2_rn(fmaxf(fmaf(f.x, s0.z, t0.z), 0.f), fmaxf(fmaf(f.y, s0.w, t0.w), 0.f));
    f = __half22float2(hv[2]);
    ov[2] = __floats2half2_rn(fmaxf(fmaf(f.x, s1.x, t1.x), 0.f), fmaxf(fmaf(f.y, s1.y, t1.y), 0.f));
    f = __half22float2(hv[3]);
    ov[3] = __floats2half2_rn(fmaxf(fmaf(f.x, s1.z, t1.z), 0.f), fmaxf(fmaf(f.y, s1.w, t1.w), 0.f));
    ((uint4*)o)[i] = out;
}

// ---------------- init: zero BN accumulators ----------------
__global__ void init_kernel() {
    int t = blockIdx.x * blockDim.x + threadIdx.x;
    if (t < 2 * D_L) g_sums_f[t] = 0.0f;
    if (t < 2 * D_G) g_sums_g[t] = 0.0f;
}

template<int C>
__global__ void bn_finalize_kernel(const float* __restrict__ sums,
                                   const float* __restrict__ gamma,
                                   const float* __restrict__ beta,
                                   float invM,
                                   float* __restrict__ scale,
                                   float* __restrict__ shift) {
    int c = threadIdx.x;
    if (c >= C) return;
    float m   = sums[c] * invM;
    float var = sums[C + c] * invM - m * m;
    float inv = rsqrtf(var + 1e-5f);
    float sc  = gamma[c] * inv;
    scale[c] = sc;
    shift[c] = beta[c] - m * sc;
}

// ---------------- L2 normalize + logit_scale ----------------
__global__ void l2norm_kernel(const float* __restrict__ G,
                              const float* __restrict__ ls,
                              float* __restrict__ out) {
    __shared__ float red[256];
    const int r = blockIdx.x, t = threadIdx.x;
    const float* g = G + (size_t)r * D_G;
    float s = 0.0f;
    for (int c = t; c < D_G; c += 256) { float v = g[c]; s = fmaf(v, v, s); }
    red[t] = s; __syncthreads();
    for (int o = 128; o > 0; o >>= 1) {
        if (t < o) red[t] += red[t + o];
        __syncthreads();
    }
    float inv = rsqrtf(red[0]);
    for (int c = t; c < D_G; c += 256)
        out[OFF_G + (size_t)r * D_G + c] = g[c] * inv;
    if (r == 0 && t == 0) out[OFF_LS] = expf(ls[0]);
}

// ---------------- fused fine epilogue: top-k select + gather + token mean ----------------
__global__ void fine_epilogue_kernel(const float* __restrict__ attn,
                                     const float* __restrict__ X2,
                                     float* __restrict__ outTop) {
    __shared__ float sv[256];
    __shared__ int   si[256];
    __shared__ int   sel[TOPK + 1];
    const int b = blockIdx.x, t = threadIdx.x;
    const float NEG = __int_as_float(0xff800000);

    float myv = (t < N_TOK - 1) ? attn[(size_t)b * (N_TOK - 1) + t] : NEG;
    if (t == 0) sel[0] = 0;
    __syncthreads();

    #pragma unroll 1
    for (int k = 0; k < TOPK; k++) {
        if (t < 256) { sv[t] = myv; si[t] = t; }
        __syncthreads();
        for (int o = 128; o > 0; o >>= 1) {
            if (t < o) {
                float v2 = sv[t + o]; int i2 = si[t + o];
                if (v2 > sv[t] || (v2 == sv[t] && i2 < si[t])) { sv[t] = v2; si[t] = i2; }
            }
            __syncthreads();
        }
        int win = si[0];
        if (t == 0)  sel[k + 1] = win + 1;
        if (t == win) myv = NEG;
        __syncthreads();
    }

    const float* xb = X2 + (size_t)b * N_TOK * D_L;
    float* ob = outTop + (size_t)b * (TOPK + 2) * D_L;
    #pragma unroll
    for (int j = 0; j < TOPK + 1; j++)
        ob[(size_t)j * D_L + t] = xb[(size_t)sel[j] * D_L + t];

    float s = 0.0f;
    #pragma unroll 4
    for (int n = 0; n < N_TOK; n++) s += xb[(size_t)n * D_L + t];
    ob[(size_t)(TOPK + 1) * D_L + t] = s * (1.0f / (float)N_TOK);
}

// ---------------- launch ----------------
extern "C" void kernel_launch(void* const* d_in, const int* in_sizes, int n_in,
                              void* d_out, int out_size)
{
    const float* image_features = (const float*)d_in[0];
    const float* fine_feat      = (const float*)d_in[1];
    const float* fine_attn      = (const float*)d_in[2];
    const float* logit_scale    = (const float*)d_in[3];
    const float* vpt_w1  = (const float*)d_in[4];
    const float* vpt_b1  = (const float*)d_in[5];
    const float* vpt_g1  = (const float*)d_in[6];
    const float* vpt_be1 = (const float*)d_in[7];
    const float* vpt_w2  = (const float*)d_in[8];
    const float* vpt_b2  = (const float*)d_in[9];
    const float* mid_w1  = (const float*)d_in[10];
    const float* mid_b1  = (const float*)d_in[11];
    const float* mid_g1  = (const float*)d_in[12];
    const float* mid_be1 = (const float*)d_in[13];
    const float* mid_w2  = (const float*)d_in[14];
    const float* mid_b2  = (const float*)d_in[15];
    float* out = (float*)d_out;

    __half *A1h, *Hfh, *W1h, *W2h, *V1h, *V2h, *gAh, *Hgh;
    float *G, *sf, *sg, *scf, *shf, *scg, *shg;
    cudaGetSymbolAddress((void**)&A1h, g_A1h);
    cudaGetSymbolAddress((void**)&Hfh, g_Hfh);
    cudaGetSymbolAddress((void**)&W1h, g_W1h);
    cudaGetSymbolAddress((void**)&W2h, g_W2h);
    cudaGetSymbolAddress((void**)&V1h, g_V1h);
    cudaGetSymbolAddress((void**)&V2h, g_V2h);
    cudaGetSymbolAddress((void**)&gAh, g_gAh);
    cudaGetSymbolAddress((void**)&Hgh, g_Hgh);
    cudaGetSymbolAddress((void**)&G,   g_G);
    cudaGetSymbolAddress((void**)&sf,  g_sums_f);  cudaGetSymbolAddress((void**)&sg, g_sums_g);
    cudaGetSymbolAddress((void**)&scf, g_scale_f); cudaGetSymbolAddress((void**)&shf, g_shift_f);
    cudaGetSymbolAddress((void**)&scg, g_scale_g); cudaGetSymbolAddress((void**)&shg, g_shift_g);

    cudaFuncSetAttribute(hgemm_kernel<true>,  cudaFuncAttributeMaxDynamicSharedMemorySize, GEMM_SMEM);
    cudaFuncSetAttribute(hgemm_kernel<false>, cudaFuncAttributeMaxDynamicSharedMemorySize, GEMM_SMEM);

    static cudaStream_t s1 = nullptr;
    static cudaEvent_t evFork = nullptr, evJoin = nullptr;
    if (s1 == nullptr) {
        cudaStreamCreateWithFlags(&s1, cudaStreamNonBlocking);
        cudaEventCreateWithFlags(&evFork, cudaEventDisableTiming);
        cudaEventCreateWithFlags(&evJoin, cudaEventDisableTiming);
    }

    auto blocks = [](int n) { return (n + 255) / 256; };

    // #1: zero BN accumulators; fork point
    init_kernel<<<8, 256>>>();
    cudaEventRecord(evFork, 0);
    cudaStreamWaitEvent(s1, evFork, 0);

    // ----- fine path (default stream) -----
    { int n4 = D_L * D_L / 4; cvt_kernel<<<blocks(n4), 256>>>(mid_w1, W1h, n4); }   // #2
    { int n4 = D_L * D_L / 4; cvt_kernel<<<blocks(n4), 256>>>(mid_w2, W2h, n4); }   // #3
    {   // fine_feat -> fp16, split in two launches (keeps ncu -s 5 on GEMM-1)
        int n4 = M_FINE * D_L / 4, h = n4 / 2;
        cvt_kernel<<<blocks(h), 256>>>(fine_feat, A1h, h);                           // #4
        cvt_kernel<<<blocks(n4 - h), 256>>>(fine_feat + (size_t)h * 4,
                                            A1h + (size_t)h * 4, n4 - h);            // #5
    }

    hgemm_kernel<true><<<dim3(D_L / 128, M_FINE / 128), 128, GEMM_SMEM>>>(           // #6 <- ncu
        A1h, W1h, mid_b1, Hfh, nullptr, sf, D_L, D_L);
    bn_finalize_kernel<D_L><<<1, D_L>>>(sf, mid_g1, mid_be1, 1.0f / (float)M_FINE, scf, shf);
    { int n8 = M_FINE * D_L / 8;
      bnrelu_kernel<<<blocks(n8), 256>>>(Hfh, scf, shf, A1h, n8, D_L / 8); }
    hgemm_kernel<false><<<dim3(D_L / 128, M_FINE / 128), 128, GEMM_SMEM>>>(
        A1h, W2h, mid_b2, nullptr, out + OFF_FINE, nullptr, D_L, D_L);

    fine_epilogue_kernel<<<B_SZ, 512>>>(fine_attn, out + OFF_FINE, out + OFF_TOP);

    // ----- global path (stream s1, overlaps fine path) -----
    { int n4 = D_G * D_L / 4; cvt_kernel<<<blocks(n4), 256, 0, s1>>>(vpt_w1, V1h, n4); }
    { int n4 = D_G * D_G / 4; cvt_kernel<<<blocks(n4), 256, 0, s1>>>(vpt_w2, V2h, n4); }
    { int n4 = B_SZ * D_L / 4; cvt_kernel<<<blocks(n4), 256, 0, s1>>>(image_features, gAh, n4); }

    hgemm_kernel<true><<<dim3(D_G / 128, B_SZ / 128), 128, GEMM_SMEM, s1>>>(
        gAh, V1h, vpt_b1, Hgh, nullptr, sg, D_G, D_L);
    bn_finalize_kernel<D_G><<<1, D_G, 0, s1>>>(sg, vpt_g1, vpt_be1, 1.0f / (float)B_SZ, scg, shg);
    { int n8 = B_SZ * D_G / 8;
      bnrelu_kernel<<<blocks(n8), 256, 0, s1>>>(Hgh, scg, shg, gAh, n8, D_G / 8); }
    hgemm_kernel<false><<<dim3(D_G / 128, B_SZ / 128), 128, GEMM_SMEM, s1>>>(
        gAh, V2h, vpt_b2, nullptr, G, nullptr, D_G, D_G);
    l2norm_kernel<<<B_SZ, 256, 0, s1>>>(G, logit_scale, out);
    cudaEventRecord(evJoin, s1);

    cudaStreamWaitEvent(0, evJoin, 0);
}